// round 5
// baseline (speedup 1.0000x reference)
#include <cuda_runtime.h>
#include <math.h>

#define BD 8
#define NN 2048
#define DD 768
#define HH 12
#define GBB 1025
#define LBB 9
#define NWW 255
#define HOPP 8
#define NCG (HH * GBB)  // 12300
#define NCL (HH * LBB)  // 108
#define PADI(n) ((n) + ((n) >> 4))

// ---------------- scratch ----------------
__device__ float g_xT[BD * DD * NN];        // (B, D, N), reused for fused output
__device__ float g_ctxp[BD * 8 * DD];
__device__ float g_ctx[BD * DD];
__device__ float g_p1[2 * 24 * BD * DD];
__device__ float g_hg[BD * DD];
__device__ float g_hl[BD * DD];
__device__ float g_pg[8 * BD * NCG];
__device__ float g_pl[8 * BD * NCL];
__device__ float g_mg[BD * NCG];
__device__ float g_ml[BD * NCL];
__device__ float2 g_tw[1025];               // exp(-i*pi*k/1024)

__device__ __forceinline__ float2 cmul(float2 a, float2 b) {
    return make_float2(a.x * b.x - a.y * b.y, a.x * b.y + a.y * b.x);
}

// ---------------- init: twiddle table ----------------
__global__ __launch_bounds__(256) void init_kernel() {
    int k = blockIdx.x * 256 + threadIdx.x;
    if (k <= 1024) {
        float ang = -(float)M_PI * (float)k * (1.0f / 1024.0f);
        float sv, cv;
        sincosf(ang, &sv, &cv);
        g_tw[k] = make_float2(cv, sv);
    }
}

// ---------------- ctx partials straight from x (coalesced) ----------------
__global__ __launch_bounds__(256) void ctx_part_kernel(const float* __restrict__ x) {
    int c = blockIdx.x * 256 + threadIdx.x;
    int b = blockIdx.y;
    int ch = blockIdx.z;
    const float* xp = x + ((size_t)b * NN + (size_t)ch * 256) * DD + c;
    float s = 0.f;
#pragma unroll 8
    for (int n = 0; n < 256; n++) s += xp[(size_t)n * DD];
    g_ctxp[(b * 8 + ch) * DD + c] = s;
}

__global__ __launch_bounds__(256) void ctx_fin_kernel() {
    int idx = blockIdx.x * 256 + threadIdx.x;  // over BD*DD = 6144
    int b = idx / DD;
    int d = idx - b * DD;
    float s = 0.f;
#pragma unroll
    for (int ch = 0; ch < 8; ch++) s += g_ctxp[(b * 8 + ch) * DD + d];
    g_ctx[idx] = s * (1.0f / (float)NN);
}

// ---------------- transpose in: x(B,N,D) -> g_xT(B,D,N) ----------------
__global__ __launch_bounds__(256) void tr_in_kernel(const float* __restrict__ x) {
    __shared__ float tile[32][33];
    int b = blockIdx.z;
    int d0 = blockIdx.x * 32;
    int n0 = blockIdx.y * 32;
    int tx = threadIdx.x, ty = threadIdx.y;

    const float* xp = x + ((size_t)(b * NN + n0 + ty)) * DD + d0 + tx;
#pragma unroll
    for (int i = 0; i < 4; i++) tile[ty + 8 * i][tx] = xp[(size_t)i * 8 * DD];
    __syncthreads();
    float* op = g_xT + ((size_t)(b * DD + d0 + ty)) * NN + n0 + tx;
#pragma unroll
    for (int i = 0; i < 4; i++) op[(size_t)i * 8 * NN] = tile[tx][ty + 8 * i];
}

// ---------------- mlp layer 1 (split-K partials, 24 chunks of 32) ----------------
__global__ __launch_bounds__(128) void mlp1_part_kernel(const float* __restrict__ w1g,
                                                        const float* __restrict__ w1l) {
    int cb = blockIdx.x % 6;
    int ks = blockIdx.x / 6;   // 0..23
    int b = blockIdx.y;
    int z = blockIdx.z;
    const float* w = z ? w1l : w1g;
    __shared__ float cs[32];
    int k0 = ks * 32;
    if (threadIdx.x < 32) cs[threadIdx.x] = g_ctx[b * DD + k0 + threadIdx.x];
    __syncthreads();
    int c = cb * 128 + threadIdx.x;
    const float* wp = w + (size_t)k0 * DD + c;
    float acc = 0.f;
#pragma unroll 8
    for (int kk = 0; kk < 32; kk++) acc += cs[kk] * wp[(size_t)kk * DD];
    g_p1[((z * 24 + ks) * BD + b) * DD + c] = acc;
}

__global__ __launch_bounds__(128) void mlp1_fin_kernel(const float* __restrict__ b1g,
                                                       const float* __restrict__ b1l) {
    int c = blockIdx.x * 128 + threadIdx.x;
    int b = blockIdx.y;
    int z = blockIdx.z;
    const float* bias = z ? b1l : b1g;
    float* out = z ? g_hl : g_hg;
    float s = bias[c];
#pragma unroll
    for (int ks = 0; ks < 24; ks++) s += g_p1[((z * 24 + ks) * BD + b) * DD + c];
    out[b * DD + c] = 0.5f * s * (1.0f + erff(s * 0.70710678118654752f));
}

// ---------------- mlp layer 2 (split-K partials) ----------------
__global__ __launch_bounds__(128) void mlp2_part_kernel(const float* __restrict__ w2g,
                                                        const float* __restrict__ w2l) {
    bool isl = (blockIdx.x == 97);
    int by = blockIdx.y;      // k-chunk
    int k0 = by * 96;
    __shared__ float hs[BD * 96];
    const float* h = isl ? g_hl : g_hg;
    for (int i = threadIdx.x; i < BD * 96; i += 128) {
        int b = i / 96, kk = i - b * 96;
        hs[i] = h[b * DD + k0 + kk];
    }
    __syncthreads();
    int ncol = isl ? NCL : NCG;
    int c = isl ? threadIdx.x : blockIdx.x * 128 + threadIdx.x;
    if (c >= ncol) return;
    const float* w = isl ? w2l : w2g;
    float* pp = isl ? g_pl : g_pg;
    float acc[BD];
#pragma unroll
    for (int b = 0; b < BD; b++) acc[b] = 0.f;
    const float* wp = w + (size_t)k0 * ncol + c;
#pragma unroll 4
    for (int kk = 0; kk < 96; kk++) {
        float wv = wp[(size_t)kk * ncol];
#pragma unroll
        for (int b = 0; b < BD; b++) acc[b] += hs[b * 96 + kk] * wv;
    }
#pragma unroll
    for (int b = 0; b < BD; b++) pp[(size_t)(by * BD + b) * ncol + c] = acc[b];
}

__global__ __launch_bounds__(128) void mlp2_fin_kernel(const float* __restrict__ b2g,
                                                       const float* __restrict__ b2l) {
    bool isl = (blockIdx.x == 97);
    int ncol = isl ? NCL : NCG;
    int c = isl ? threadIdx.x : blockIdx.x * 128 + threadIdx.x;
    if (c >= ncol) return;
    int b = blockIdx.y;
    const float* bias = isl ? b2l : b2g;
    const float* pp = isl ? g_pl : g_pg;
    float* out = isl ? g_ml : g_mg;
    float s = bias[c];
#pragma unroll
    for (int ks = 0; ks < 8; ks++) s += pp[(size_t)(ks * BD + b) * ncol + c];
    out[(size_t)b * ncol + c] = tanhf(s);
}

// ---------------- radix-4 Stockham FFT (1024 pts, 5 stages) ----------------
template <bool INV>
__device__ __forceinline__ void fft1024(float2* src, float2* dst, const float2* tws, int tid) {
#pragma unroll
    for (int t = 0; t < 5; t++) {
        const int s = 1 << (2 * t);
        int q = tid & (s - 1);
        int ps = tid - q;
        float2 a = src[tid];
        float2 b = src[tid + 256];
        float2 c = src[tid + 512];
        float2 d = src[tid + 768];
        float2 w1 = tws[2 * ps];
        float2 w2 = tws[4 * ps];
        if (INV) { w1.y = -w1.y; w2.y = -w2.y; }
        float2 w3 = cmul(w1, w2);
        float2 apc = make_float2(a.x + c.x, a.y + c.y);
        float2 amc = make_float2(a.x - c.x, a.y - c.y);
        float2 bpd = make_float2(b.x + d.x, b.y + d.y);
        float2 bmd = make_float2(b.x - d.x, b.y - d.y);
        int o = 4 * tid - 3 * q;
        dst[o] = make_float2(apc.x + bpd.x, apc.y + bpd.y);
        float2 t1, t3;
        if (!INV) {
            t1 = make_float2(amc.x + bmd.y, amc.y - bmd.x);
            t3 = make_float2(amc.x - bmd.y, amc.y + bmd.x);
        } else {
            t1 = make_float2(amc.x - bmd.y, amc.y + bmd.x);
            t3 = make_float2(amc.x + bmd.y, amc.y - bmd.x);
        }
        dst[o + s] = cmul(t1, w1);
        dst[o + 2 * s] = cmul(make_float2(apc.x - bpd.x, apc.y - bpd.y), w2);
        dst[o + 3 * s] = cmul(t3, w3);
        __syncthreads();
        float2* tmp = src; src = dst; dst = tmp;
    }
}

__device__ __forceinline__ float2 filt_modrelu(float2 v, float g, float bias, float prescale) {
    v.x *= prescale * g;
    v.y *= prescale * g;
    float a = sqrtf(v.x * v.x + v.y * v.y);
    float sc = fmaxf(a + bias, 0.0f) / fmaxf(a, 1e-6f);
    v.x *= sc;
    v.y *= sc;
    return v;
}

__global__ __launch_bounds__(256) void spectral_kernel(
    const float* __restrict__ base_g, const float* __restrict__ base_l,
    const float* __restrict__ bias_g, const float* __restrict__ bias_l,
    const float* __restrict__ fusion_w) {
    __shared__ float2 bufA[1024];
    __shared__ float2 uB[1088];        // union: padded s_time (2176 floats) / bufB (1024 float2)
    __shared__ float s_xl[2176];       // padded overlap-add accumulator
    __shared__ float2 tws[1025];
    float2* bufB = uB;
    float* s_time = (float*)uB;

    const int tid = threadIdx.x;
    const int blk = blockIdx.x;
    const int b = blk / DD;
    const int c = blk - b * DD;
    const int h = c >> 6;
    const float invs = 0.022097086912079608f;  // 1/sqrt(2048)

    for (int k = tid; k <= 1024; k += 256) tws[k] = g_tw[k];

    float* row = g_xT + (size_t)blk * NN;
    {
        const float4* src4 = (const float4*)row;
        for (int i = tid; i < 512; i += 256) {
            float4 v = src4[i];
            int p = PADI(4 * i);   // 4i..4i+3 stay inside one 16-group
            s_time[p] = v.x;
            s_time[p + 1] = v.y;
            s_time[p + 2] = v.z;
            s_time[p + 3] = v.w;
        }
        for (int n = tid; n < 2176; n += 256) s_xl[n] = 0.f;
    }
    __syncthreads();

    // -------- local STFT path (padded SMEM, conflict-free; j=0 skipped: hann(0)=0) ----
    {
        const float c16[16] = {1.f, 0.92387953251128674f, 0.70710678118654752f, 0.38268343236508977f,
                               0.f, -0.38268343236508977f, -0.70710678118654752f, -0.92387953251128674f,
                               -1.f, -0.92387953251128674f, -0.70710678118654752f, -0.38268343236508977f,
                               0.f, 0.38268343236508977f, 0.70710678118654752f, 0.92387953251128674f};
        const float s16[16] = {0.f, 0.38268343236508977f, 0.70710678118654752f, 0.92387953251128674f,
                               1.f, 0.92387953251128674f, 0.70710678118654752f, 0.38268343236508977f,
                               0.f, -0.38268343236508977f, -0.70710678118654752f, -0.92387953251128674f,
                               -1.f, -0.92387953251128674f, -0.70710678118654752f, -0.38268343236508977f};
        const float hwin[16] = {0.f, 0.03806023374435663f, 0.14644660940672624f, 0.30865828381745508f,
                                0.5f, 0.69134171618254492f, 0.85355339059327376f, 0.96193976625564337f,
                                1.f, 0.96193976625564337f, 0.85355339059327376f, 0.69134171618254492f,
                                0.5f, 0.30865828381745508f, 0.14644660940672624f, 0.03806023374435663f};
        const float* mlb = g_ml + (b * HH + h) * LBB;
        const float* blb = base_l + h * LBB;
        const float* bib = bias_l + h * LBB;
        float gl[LBB], bl9[LBB];
#pragma unroll
        for (int k = 0; k < LBB; k++) {
            gl[k] = blb[k] + mlb[k];
            bl9[k] = bib[k];
        }
        for (int par = 0; par < 2; par++) {
            int nw = 2 * tid + par;
            if (nw < NWW) {
                int base = nw * HOPP;
                float t16[16];
#pragma unroll
                for (int j = 1; j < 16; j++) t16[j] = s_time[PADI(base + j)] * hwin[j];
                float re[LBB], im[LBB];
#pragma unroll
                for (int k = 0; k < LBB; k++) {
                    float r = 0.f, ii = 0.f;
#pragma unroll
                    for (int j = 1; j < 16; j++) {
                        int id = (k * j) & 15;
                        r += t16[j] * c16[id];
                        ii -= t16[j] * s16[id];
                    }
                    r *= 0.25f;
                    ii *= 0.25f;
                    r *= gl[k];
                    ii *= gl[k];
                    float a = sqrtf(r * r + ii * ii);
                    float sc = fmaxf(a + bl9[k], 0.0f) / fmaxf(a, 1e-6f);
                    re[k] = r * sc;
                    im[k] = ii * sc;
                }
#pragma unroll
                for (int j = 1; j < 16; j++) {
                    float y = re[0];
#pragma unroll
                    for (int k = 1; k < 8; k++) {
                        int id = (k * j) & 15;
                        y += 2.0f * (re[k] * c16[id] - im[k] * s16[id]);
                    }
                    {
                        int id = (8 * j) & 15;
                        y += re[8] * c16[id] - im[8] * s16[id];
                    }
                    y *= 0.25f * hwin[j];
                    s_xl[PADI(base + j)] += y;
                }
            }
            __syncthreads();
        }
    }

    // -------- global path --------
    // pack even/odd into bufA (s_time aliases bufB; dead after this)
    for (int m = tid; m < 1024; m += 256) {
        int p = PADI(2 * m);  // 2m, 2m+1 share a 16-group
        bufA[m] = make_float2(s_time[p], s_time[p + 1]);
    }
    __syncthreads();

    fft1024<false>(bufA, bufB, tws, tid);  // result in bufB

    // merged: unpack Z -> X (registers) -> filter/modrelu -> repack G (bufA)
    {
        const float* mgb = g_mg + (b * HH + h) * GBB;
        const float* bgb = base_g + h * GBB;
        const float* bib = bias_g + h * GBB;
        float2* Z = bufB;
        float2* G = bufA;
        for (int k = tid; k <= 512; k += 256) {
            float2 Zk = Z[k & 1023];
            float2 Zm = Z[(1024 - k) & 1023];
            float2 E = make_float2(0.5f * (Zk.x + Zm.x), 0.5f * (Zk.y - Zm.y));
            float2 O = make_float2(0.5f * (Zk.y + Zm.y), -0.5f * (Zk.x - Zm.x));
            float2 Xk = cmul(tws[k], O);
            Xk.x += E.x;
            Xk.y += E.y;
            Xk = filt_modrelu(Xk, bgb[k] + mgb[k], bib[k], invs);
            float2 Xm;
            if (k < 512) {
                int kk = 1024 - k;
                float2 Ec = make_float2(E.x, -E.y);
                float2 Oc = make_float2(O.x, -O.y);
                Xm = cmul(tws[kk], Oc);
                Xm.x += Ec.x;
                Xm.y += Ec.y;
                Xm = filt_modrelu(Xm, bgb[kk] + mgb[kk], bib[kk], invs);
            } else {
                Xm = Xk;
            }
            // G[k] from (Xa=Xk, Xb=Xm)
            {
                float2 S = make_float2(Xk.x + Xm.x, Xk.y - Xm.y);
                float2 Dd = make_float2(Xk.x - Xm.x, Xk.y + Xm.y);
                float2 wc = make_float2(tws[k].x, -tws[k].y);
                float2 t = cmul(wc, Dd);
                G[k] = make_float2(S.x - t.y, S.y + t.x);
            }
            // G[1024-k] from (Xa=Xm, Xb=Xk)
            if (k > 0 && k < 512) {
                int jj = 1024 - k;
                float2 S = make_float2(Xm.x + Xk.x, Xm.y - Xk.y);
                float2 Dd = make_float2(Xm.x - Xk.x, Xm.y + Xk.y);
                float2 wc = make_float2(tws[jj].x, -tws[jj].y);
                float2 t = cmul(wc, Dd);
                G[jj] = make_float2(S.x - t.y, S.y + t.x);
            }
        }
    }
    __syncthreads();

    fft1024<true>(bufA, bufB, tws, tid);  // inverse: result in bufB

    // fuse + contiguous write back into g_xT
    {
        float fw0 = fusion_w[0];
        float fw1 = fusion_w[1];
        float2* orow2 = (float2*)row;
        for (int m = tid; m < 1024; m += 256) {
            float2 zc = bufB[m];
            int p = PADI(2 * m);
            orow2[m] = make_float2(fw0 * (zc.x * invs) + fw1 * s_xl[p],
                                   fw0 * (zc.y * invs) + fw1 * s_xl[p + 1]);
        }
    }
}

// ---------------- fused transpose-out + residual + layernorm ----------------
__global__ __launch_bounds__(256) void ln_fused_kernel(const float* __restrict__ x,
                                                       const float* __restrict__ gamma,
                                                       const float* __restrict__ beta,
                                                       float* __restrict__ out) {
    __shared__ float tile[DD * 9];   // [d][j], row stride 9 (pad)
    int n0 = blockIdx.x * 8;
    int b = blockIdx.y;
    int tid = threadIdx.x;

    const float* gx = g_xT + (size_t)b * DD * NN + n0;
    for (int idx = tid; idx < DD * 8; idx += 256) {
        int d = idx >> 3;
        int j = idx & 7;
        tile[d * 9 + j] = gx[(size_t)d * NN + j];
    }
    __syncthreads();

    int w = tid >> 5;
    int lane = tid & 31;
    int n = n0 + w;
    const float* xr = x + ((size_t)b * NN + n) * DD;
    float* orow = out + ((size_t)b * NN + n) * DD;

    float y[24];
    float sum = 0.f;
#pragma unroll
    for (int i = 0; i < 24; i++) {
        int d = i * 32 + lane;
        float v = xr[d] + tile[d * 9 + w];
        y[i] = v;
        sum += v;
    }
#pragma unroll
    for (int o = 16; o > 0; o >>= 1) sum += __shfl_xor_sync(0xffffffffu, sum, o);
    float mu = sum * (1.0f / (float)DD);
    float vs = 0.f;
#pragma unroll
    for (int i = 0; i < 24; i++) {
        float d0 = y[i] - mu;
        y[i] = d0;
        vs += d0 * d0;
    }
#pragma unroll
    for (int o = 16; o > 0; o >>= 1) vs += __shfl_xor_sync(0xffffffffu, vs, o);
    float rstd = rsqrtf(vs * (1.0f / (float)DD) + 1e-5f);
#pragma unroll
    for (int i = 0; i < 24; i++) {
        int d = i * 32 + lane;
        orow[d] = y[i] * rstd * gamma[d] + beta[d];
    }
}

// ---------------- launch (2-stream overlap: MLP chain || transpose) ----------------
static cudaStream_t g_s2 = nullptr;
static cudaEvent_t g_ev_fork = nullptr;
static cudaEvent_t g_ev_join = nullptr;

extern "C" void kernel_launch(void* const* d_in, const int* in_sizes, int n_in,
                              void* d_out, int out_size) {
    const float* x = (const float*)d_in[0];
    const float* bf_g = (const float*)d_in[1];
    const float* bf_l = (const float*)d_in[2];
    const float* mb_g = (const float*)d_in[3];
    const float* mb_l = (const float*)d_in[4];
    const float* w1g = (const float*)d_in[5];
    const float* b1g = (const float*)d_in[6];
    const float* w2g = (const float*)d_in[7];
    const float* b2g = (const float*)d_in[8];
    const float* w1l = (const float*)d_in[9];
    const float* b1l = (const float*)d_in[10];
    const float* w2l = (const float*)d_in[11];
    const float* b2l = (const float*)d_in[12];
    const float* fw = (const float*)d_in[13];
    const float* gamma = (const float*)d_in[14];
    const float* beta = (const float*)d_in[15];
    float* out = (float*)d_out;

    if (!g_s2) {
        cudaStreamCreateWithFlags(&g_s2, cudaStreamNonBlocking);
        cudaEventCreateWithFlags(&g_ev_fork, cudaEventDisableTiming);
        cudaEventCreateWithFlags(&g_ev_join, cudaEventDisableTiming);
    }

    // fork: MLP chain on s2, transpose path on default stream
    cudaEventRecord(g_ev_fork, 0);
    cudaStreamWaitEvent(g_s2, g_ev_fork, 0);

    ctx_part_kernel<<<dim3(3, 8, 8), 256, 0, g_s2>>>(x);
    ctx_fin_kernel<<<24, 256, 0, g_s2>>>();
    mlp1_part_kernel<<<dim3(144, 8, 2), 128, 0, g_s2>>>(w1g, w1l);
    mlp1_fin_kernel<<<dim3(6, 8, 2), 128, 0, g_s2>>>(b1g, b1l);
    mlp2_part_kernel<<<dim3(98, 8), 128, 0, g_s2>>>(w2g, w2l);
    mlp2_fin_kernel<<<dim3(98, 8), 128, 0, g_s2>>>(b2g, b2l);
    cudaEventRecord(g_ev_join, g_s2);

    init_kernel<<<5, 256>>>();
    tr_in_kernel<<<dim3(24, 64, 8), dim3(32, 8)>>>(x);

    // join: spectral needs both g_xT and g_mg/g_ml
    cudaStreamWaitEvent(0, g_ev_join, 0);
    spectral_kernel<<<BD * DD, 256>>>(bf_g, bf_l, mb_g, mb_l, fw);
    ln_fused_kernel<<<dim3(256, 8), 256>>>(x, gamma, beta, out);
}

// round 6
// speedup vs baseline: 1.2019x; 1.2019x over previous
#include <cuda_runtime.h>
#include <math.h>

#define BD 8
#define NN 2048
#define DD 768
#define HH 12
#define GBB 1025
#define LBB 9
#define NWW 255
#define HOPP 8
#define NCG (HH * GBB)  // 12300
#define NCL (HH * LBB)  // 108
#define PADI(n) ((n) + ((n) >> 4))

// ---------------- scratch ----------------
__device__ float g_xT[BD * DD * NN];        // (B, D, N), reused for fused output
__device__ float g_ctxp[BD * 8 * DD];
__device__ float g_p1[2 * 24 * BD * DD];
__device__ float g_pg[8 * BD * NCG];
__device__ float g_pl[8 * BD * NCL];
__device__ float g_mg[BD * NCG];
__device__ float g_ml[BD * NCL];
__device__ float2 g_tw[1025];               // exp(-i*pi*k/1024)

__device__ __forceinline__ float2 cmul(float2 a, float2 b) {
    return make_float2(a.x * b.x - a.y * b.y, a.x * b.y + a.y * b.x);
}
__device__ __forceinline__ float2 cadd(float2 a, float2 b) {
    return make_float2(a.x + b.x, a.y + b.y);
}
__device__ __forceinline__ float2 csub(float2 a, float2 b) {
    return make_float2(a.x - b.x, a.y - b.y);
}

// modrelu rescale: max(a+bias,0)/max(a,1e-6) with a=sqrt(m)
__device__ __forceinline__ float mr_scale(float m, float bias) {
    if (m >= 1e-12f) return fmaxf(fmaf(bias, rsqrtf(m), 1.0f), 0.0f);
    return fmaxf(sqrtf(m) + bias, 0.0f) * 1e6f;
}

__device__ __forceinline__ float2 filt_modrelu(float2 v, float pg, float bias) {
    v.x *= pg;
    v.y *= pg;
    float sc = mr_scale(v.x * v.x + v.y * v.y, bias);
    v.x *= sc;
    v.y *= sc;
    return v;
}

// ---------------- ctx partials straight from x (coalesced) + twiddle init ----------------
__global__ __launch_bounds__(256) void ctx_part_kernel(const float* __restrict__ x) {
    int c = blockIdx.x * 256 + threadIdx.x;
    int b = blockIdx.y;
    int ch = blockIdx.z;
    const float* xp = x + ((size_t)b * NN + (size_t)ch * 256) * DD + c;
    float s = 0.f;
#pragma unroll 8
    for (int n = 0; n < 256; n++) s += xp[(size_t)n * DD];
    g_ctxp[(b * 8 + ch) * DD + c] = s;

    // fold in twiddle table init (5 of the b==0 blocks)
    int bid = blockIdx.z * 3 + blockIdx.x;
    if (blockIdx.y == 0 && bid < 5) {
        int k = bid * 256 + threadIdx.x;
        if (k <= 1024) {
            float ang = -(float)M_PI * (float)k * (1.0f / 1024.0f);
            float sv, cv;
            sincosf(ang, &sv, &cv);
            g_tw[k] = make_float2(cv, sv);
        }
    }
}

// ---------------- mlp layer 1 (split-K partials, ctx reduce folded in) ----------------
__global__ __launch_bounds__(128) void mlp1_part_kernel(const float* __restrict__ w1g,
                                                        const float* __restrict__ w1l) {
    int cb = blockIdx.x % 6;
    int ks = blockIdx.x / 6;   // 0..23
    int b = blockIdx.y;
    int z = blockIdx.z;
    const float* w = z ? w1l : w1g;
    __shared__ float cs[32];
    int k0 = ks * 32;
    if (threadIdx.x < 32) {
        float s = 0.f;
#pragma unroll
        for (int ch = 0; ch < 8; ch++) s += g_ctxp[(b * 8 + ch) * DD + k0 + threadIdx.x];
        cs[threadIdx.x] = s * (1.0f / (float)NN);
    }
    __syncthreads();
    int c = cb * 128 + threadIdx.x;
    const float* wp = w + (size_t)k0 * DD + c;
    float acc = 0.f;
#pragma unroll 8
    for (int kk = 0; kk < 32; kk++) acc += cs[kk] * wp[(size_t)kk * DD];
    g_p1[((z * 24 + ks) * BD + b) * DD + c] = acc;
}

// ---------------- mlp layer 2 (split-K partials, GELU finish of layer1 folded in) -----
__global__ __launch_bounds__(128) void mlp2_part_kernel(const float* __restrict__ w2g,
                                                        const float* __restrict__ w2l,
                                                        const float* __restrict__ b1g,
                                                        const float* __restrict__ b1l) {
    bool isl = (blockIdx.x == 97);
    int by = blockIdx.y;      // k-chunk
    int k0 = by * 96;
    __shared__ float hs[BD * 96];
    const float* bias1 = isl ? b1l : b1g;
    const float* p1 = g_p1 + (isl ? 24 * BD * DD : 0);
    for (int i = threadIdx.x; i < BD * 96; i += 128) {
        int b = i / 96, kk = i - b * 96;
        int k = k0 + kk;
        float s = bias1[k];
#pragma unroll
        for (int ks = 0; ks < 24; ks++) s += p1[(size_t)(ks * BD + b) * DD + k];
        hs[i] = 0.5f * s * (1.0f + erff(s * 0.70710678118654752f));
    }
    __syncthreads();
    int ncol = isl ? NCL : NCG;
    int c = isl ? threadIdx.x : blockIdx.x * 128 + threadIdx.x;
    if (c >= ncol) return;
    const float* w = isl ? w2l : w2g;
    float* pp = isl ? g_pl : g_pg;
    float acc[BD];
#pragma unroll
    for (int b = 0; b < BD; b++) acc[b] = 0.f;
    const float* wp = w + (size_t)k0 * ncol + c;
#pragma unroll 4
    for (int kk = 0; kk < 96; kk++) {
        float wv = wp[(size_t)kk * ncol];
#pragma unroll
        for (int b = 0; b < BD; b++) acc[b] += hs[b * 96 + kk] * wv;
    }
#pragma unroll
    for (int b = 0; b < BD; b++) pp[(size_t)(by * BD + b) * ncol + c] = acc[b];
}

__global__ __launch_bounds__(128) void mlp2_fin_kernel(const float* __restrict__ b2g,
                                                       const float* __restrict__ b2l) {
    bool isl = (blockIdx.x == 97);
    int ncol = isl ? NCL : NCG;
    int c = isl ? threadIdx.x : blockIdx.x * 128 + threadIdx.x;
    if (c >= ncol) return;
    int b = blockIdx.y;
    const float* bias = isl ? b2l : b2g;
    const float* pp = isl ? g_pl : g_pg;
    float* out = isl ? g_ml : g_mg;
    float s = bias[c];
#pragma unroll
    for (int ks = 0; ks < 8; ks++) s += pp[(size_t)(ks * BD + b) * ncol + c];
    out[(size_t)b * ncol + c] = tanhf(s);
}

// ---------------- transpose in: x(B,N,D) -> g_xT(B,D,N) ----------------
__global__ __launch_bounds__(256) void tr_in_kernel(const float* __restrict__ x) {
    __shared__ float tile[32][33];
    int b = blockIdx.z;
    int d0 = blockIdx.x * 32;
    int n0 = blockIdx.y * 32;
    int tx = threadIdx.x, ty = threadIdx.y;

    const float* xp = x + ((size_t)(b * NN + n0 + ty)) * DD + d0 + tx;
#pragma unroll
    for (int i = 0; i < 4; i++) tile[ty + 8 * i][tx] = xp[(size_t)i * 8 * DD];
    __syncthreads();
    float* op = g_xT + ((size_t)(b * DD + d0 + ty)) * NN + n0 + tx;
#pragma unroll
    for (int i = 0; i < 4; i++) op[(size_t)i * 8 * NN] = tile[tx][ty + 8 * i];
}

// ---------------- radix-4 Stockham FFT (1024 pts, 5 stages) ----------------
template <bool INV>
__device__ __forceinline__ void fft1024(float2* src, float2* dst, const float2* tws, int tid) {
#pragma unroll
    for (int t = 0; t < 5; t++) {
        const int s = 1 << (2 * t);
        int q = tid & (s - 1);
        int ps = tid - q;
        float2 a = src[tid];
        float2 b = src[tid + 256];
        float2 c = src[tid + 512];
        float2 d = src[tid + 768];
        float2 w1 = tws[2 * ps];
        float2 w2 = tws[4 * ps];
        if (INV) { w1.y = -w1.y; w2.y = -w2.y; }
        float2 w3 = cmul(w1, w2);
        float2 apc = cadd(a, c);
        float2 amc = csub(a, c);
        float2 bpd = cadd(b, d);
        float2 bmd = csub(b, d);
        int o = 4 * tid - 3 * q;
        dst[o] = cadd(apc, bpd);
        float2 t1, t3;
        if (!INV) {
            t1 = make_float2(amc.x + bmd.y, amc.y - bmd.x);
            t3 = make_float2(amc.x - bmd.y, amc.y + bmd.x);
        } else {
            t1 = make_float2(amc.x - bmd.y, amc.y + bmd.x);
            t3 = make_float2(amc.x + bmd.y, amc.y - bmd.x);
        }
        dst[o + s] = cmul(t1, w1);
        dst[o + 2 * s] = cmul(csub(apc, bpd), w2);
        dst[o + 3 * s] = cmul(t3, w3);
        __syncthreads();
        float2* tmp = src; src = dst; dst = tmp;
    }
}

__global__ __launch_bounds__(256) void spectral_kernel(
    const float* __restrict__ base_g, const float* __restrict__ base_l,
    const float* __restrict__ bias_g, const float* __restrict__ bias_l,
    const float* __restrict__ fusion_w) {
    __shared__ float2 bufA[1024];
    __shared__ float2 uB[1088];        // union: padded s_time (2176 floats) / bufB (1024 float2)
    __shared__ float s_xl[2176];       // padded overlap-add accumulator
    __shared__ float2 tws[1025];
    __shared__ float2 glb[9];          // {0.25*(base+ml), bias} per local freq
    float2* bufB = uB;
    float* s_time = (float*)uB;

    const int tid = threadIdx.x;
    const int blk = blockIdx.x;
    const int b = blk / DD;
    const int c = blk - b * DD;
    const int h = c >> 6;
    const float invs = 0.022097086912079608f;  // 1/sqrt(2048)
    const float r2 = 0.70710678118654752f;

    for (int k = tid; k <= 1024; k += 256) tws[k] = g_tw[k];
    if (tid < 9)
        glb[tid] = make_float2(0.25f * (base_l[h * LBB + tid] + g_ml[(b * HH + h) * LBB + tid]),
                               bias_l[h * LBB + tid]);

    float* row = g_xT + (size_t)blk * NN;
    {
        const float4* src4 = (const float4*)row;
        for (int i = tid; i < 512; i += 256) {
            float4 v = src4[i];
            int p = PADI(4 * i);
            s_time[p] = v.x;
            s_time[p + 1] = v.y;
            s_time[p + 2] = v.z;
            s_time[p + 3] = v.w;
        }
        for (int n = tid; n < 2176; n += 256) s_xl[n] = 0.f;
    }
    __syncthreads();

    // -------- local STFT path: packed real FFT-16 via complex FFT8 in registers ------
    {
        const float hq[16] = {0.f, 0.25f * 0.03806023374435663f, 0.25f * 0.14644660940672624f,
                              0.25f * 0.30865828381745508f, 0.25f * 0.5f, 0.25f * 0.69134171618254492f,
                              0.25f * 0.85355339059327376f, 0.25f * 0.96193976625564337f, 0.25f * 1.f,
                              0.25f * 0.96193976625564337f, 0.25f * 0.85355339059327376f,
                              0.25f * 0.69134171618254492f, 0.25f * 0.5f, 0.25f * 0.30865828381745508f,
                              0.25f * 0.14644660940672624f, 0.25f * 0.03806023374435663f};
        const float hw[16] = {0.f, 0.03806023374435663f, 0.14644660940672624f, 0.30865828381745508f,
                              0.5f, 0.69134171618254492f, 0.85355339059327376f, 0.96193976625564337f,
                              1.f, 0.96193976625564337f, 0.85355339059327376f, 0.69134171618254492f,
                              0.5f, 0.30865828381745508f, 0.14644660940672624f, 0.03806023374435663f};
        // w16^k = (cw[k], -sw[k]), k=0..8
        const float cw[9] = {1.f, 0.92387953251128674f, r2, 0.38268343236508977f, 0.f,
                             -0.38268343236508977f, -r2, -0.92387953251128674f, -1.f};
        const float sw[9] = {0.f, 0.38268343236508977f, r2, 0.92387953251128674f, 1.f,
                             0.92387953251128674f, r2, 0.38268343236508977f, 0.f};

        for (int par = 0; par < 2; par++) {
            int nw = 2 * tid + par;
            if (nw < NWW) {
                int base = nw * HOPP;
                float tw[16];
                tw[0] = 0.f;
#pragma unroll
                for (int j = 1; j < 16; j++) tw[j] = s_time[PADI(base + j)] * hw[j];

                // pack: z[m] = (t[2m], t[2m+1])
                float2 z[8];
#pragma unroll
                for (int m = 0; m < 8; m++) z[m] = make_float2(tw[2 * m], tw[2 * m + 1]);

                // forward FFT8 (DIF, w = e^{-2pi i/8}), output bit-reversed -> Z[]
                float2 Z[8];
                {
                    float2 a0 = cadd(z[0], z[4]), d0 = csub(z[0], z[4]);
                    float2 a1 = cadd(z[1], z[5]), d1 = csub(z[1], z[5]);
                    float2 a2 = cadd(z[2], z[6]), d2 = csub(z[2], z[6]);
                    float2 a3 = cadd(z[3], z[7]), d3 = csub(z[3], z[7]);
                    float2 a4 = d0;
                    float2 a5 = make_float2(r2 * (d1.x + d1.y), r2 * (d1.y - d1.x));
                    float2 a6 = make_float2(d2.y, -d2.x);
                    float2 a7 = make_float2(r2 * (d3.y - d3.x), -r2 * (d3.x + d3.y));

                    float2 b0 = cadd(a0, a2), b2 = csub(a0, a2);
                    float2 b1 = cadd(a1, a3), t13 = csub(a1, a3);
                    float2 b3 = make_float2(t13.y, -t13.x);
                    float2 b4 = cadd(a4, a6), b6 = csub(a4, a6);
                    float2 b5 = cadd(a5, a7), t57 = csub(a5, a7);
                    float2 b7 = make_float2(t57.y, -t57.x);

                    Z[0] = cadd(b0, b1);
                    Z[4] = csub(b0, b1);
                    Z[2] = cadd(b2, b3);
                    Z[6] = csub(b2, b3);
                    Z[1] = cadd(b4, b5);
                    Z[5] = csub(b4, b5);
                    Z[3] = cadd(b6, b7);
                    Z[7] = csub(b6, b7);
                }

                // unpack to rfft16 spectrum + filter + modrelu
                float2 X[9];
#pragma unroll
                for (int k = 0; k <= 4; k++) {
                    float2 Zk = Z[k];
                    float2 Zm = Z[(8 - k) & 7];
                    float2 E = make_float2(0.5f * (Zk.x + Zm.x), 0.5f * (Zk.y - Zm.y));
                    float2 O = make_float2(0.5f * (Zk.y + Zm.y), -0.5f * (Zk.x - Zm.x));
                    float2 w = make_float2(cw[k], -sw[k]);
                    float2 Xk = cadd(E, cmul(w, O));
                    float2 gb = glb[k];
                    X[k] = filt_modrelu(Xk, gb.x, gb.y);
                    if (k > 0 && k < 4) {
                        int kk = 8 - k;
                        float2 wm = make_float2(cw[kk], -sw[kk]);
                        float2 Xm = cadd(make_float2(E.x, -E.y), cmul(wm, make_float2(O.x, -O.y)));
                        float2 gb2 = glb[kk];
                        X[kk] = filt_modrelu(Xm, gb2.x, gb2.y);
                    } else if (k == 0) {
                        // X[8] = conj(E) - conj(O)
                        float2 Xm = make_float2(E.x - O.x, O.y - E.y);
                        float2 gb2 = glb[8];
                        X[8] = filt_modrelu(Xm, gb2.x, gb2.y);
                    }
                }

                // repack: G[m] = S + i*conj(w16^m)*D
                float2 G[8];
#pragma unroll
                for (int m = 0; m < 8; m++) {
                    float2 Xa = X[m];
                    float2 Xb = X[8 - m];
                    float2 S = make_float2(Xa.x + Xb.x, Xa.y - Xb.y);
                    float2 D = make_float2(Xa.x - Xb.x, Xa.y + Xb.y);
                    float2 wc = make_float2(cw[m], sw[m]);
                    float2 t = cmul(wc, D);
                    G[m] = make_float2(S.x - t.y, S.y + t.x);
                }

                // inverse FFT8 (conjugate twiddles), output bit-reversed -> g[]
                float2 g[8];
                {
                    float2 a0 = cadd(G[0], G[4]), d0 = csub(G[0], G[4]);
                    float2 a1 = cadd(G[1], G[5]), d1 = csub(G[1], G[5]);
                    float2 a2 = cadd(G[2], G[6]), d2 = csub(G[2], G[6]);
                    float2 a3 = cadd(G[3], G[7]), d3 = csub(G[3], G[7]);
                    float2 a4 = d0;
                    float2 a5 = make_float2(r2 * (d1.x - d1.y), r2 * (d1.x + d1.y));
                    float2 a6 = make_float2(-d2.y, d2.x);
                    float2 a7 = make_float2(-r2 * (d3.x + d3.y), r2 * (d3.x - d3.y));

                    float2 b0 = cadd(a0, a2), b2 = csub(a0, a2);
                    float2 b1 = cadd(a1, a3), t13 = csub(a1, a3);
                    float2 b3 = make_float2(-t13.y, t13.x);
                    float2 b4 = cadd(a4, a6), b6 = csub(a4, a6);
                    float2 b5 = cadd(a5, a7), t57 = csub(a5, a7);
                    float2 b7 = make_float2(-t57.y, t57.x);

                    g[0] = cadd(b0, b1);
                    g[4] = csub(b0, b1);
                    g[2] = cadd(b2, b3);
                    g[6] = csub(b2, b3);
                    g[1] = cadd(b4, b5);
                    g[5] = csub(b4, b5);
                    g[3] = cadd(b6, b7);
                    g[7] = csub(b6, b7);
                }

                // overlap-add (x0.25 ortho + hann folded into hq); j=0 skipped (hq=0)
#pragma unroll
                for (int m = 0; m < 8; m++) {
                    if (m > 0) s_xl[PADI(base + 2 * m)] += g[m].x * hq[2 * m];
                    s_xl[PADI(base + 2 * m + 1)] += g[m].y * hq[2 * m + 1];
                }
            }
            __syncthreads();
        }
    }

    // -------- global path --------
    for (int m = tid; m < 1024; m += 256) {
        int p = PADI(2 * m);
        bufA[m] = make_float2(s_time[p], s_time[p + 1]);
    }
    __syncthreads();

    fft1024<false>(bufA, bufB, tws, tid);  // result in bufB

    // merged: unpack Z -> X -> filter/modrelu -> repack G (bufA)
    {
        const float* mgb = g_mg + (b * HH + h) * GBB;
        const float* bgb = base_g + h * GBB;
        const float* bib = bias_g + h * GBB;
        float2* Z = bufB;
        float2* G = bufA;
        for (int k = tid; k <= 512; k += 256) {
            float2 Zk = Z[k & 1023];
            float2 Zm = Z[(1024 - k) & 1023];
            float2 E = make_float2(0.5f * (Zk.x + Zm.x), 0.5f * (Zk.y - Zm.y));
            float2 O = make_float2(0.5f * (Zk.y + Zm.y), -0.5f * (Zk.x - Zm.x));
            float2 Xk = cadd(E, cmul(tws[k], O));
            Xk = filt_modrelu(Xk, invs * (bgb[k] + mgb[k]), bib[k]);
            float2 Xm;
            if (k < 512) {
                int kk = 1024 - k;
                Xm = cadd(make_float2(E.x, -E.y), cmul(tws[kk], make_float2(O.x, -O.y)));
                Xm = filt_modrelu(Xm, invs * (bgb[kk] + mgb[kk]), bib[kk]);
            } else {
                Xm = Xk;
            }
            {
                float2 S = make_float2(Xk.x + Xm.x, Xk.y - Xm.y);
                float2 Dd = make_float2(Xk.x - Xm.x, Xk.y + Xm.y);
                float2 wc = make_float2(tws[k].x, -tws[k].y);
                float2 t = cmul(wc, Dd);
                G[k] = make_float2(S.x - t.y, S.y + t.x);
            }
            if (k > 0 && k < 512) {
                int jj = 1024 - k;
                float2 S = make_float2(Xm.x + Xk.x, Xm.y - Xk.y);
                float2 Dd = make_float2(Xm.x - Xk.x, Xm.y + Xk.y);
                float2 wc = make_float2(tws[jj].x, -tws[jj].y);
                float2 t = cmul(wc, Dd);
                G[jj] = make_float2(S.x - t.y, S.y + t.x);
            }
        }
    }
    __syncthreads();

    fft1024<true>(bufA, bufB, tws, tid);  // inverse: result in bufB

    // fuse + contiguous write back into g_xT
    {
        float fw0 = fusion_w[0];
        float fw1 = fusion_w[1];
        float2* orow2 = (float2*)row;
        for (int m = tid; m < 1024; m += 256) {
            float2 zc = bufB[m];
            int p = PADI(2 * m);
            orow2[m] = make_float2(fw0 * (zc.x * invs) + fw1 * s_xl[p],
                                   fw0 * (zc.y * invs) + fw1 * s_xl[p + 1]);
        }
    }
}

// ---------------- fused transpose-out + residual + layernorm ----------------
__global__ __launch_bounds__(256) void ln_fused_kernel(const float* __restrict__ x,
                                                       const float* __restrict__ gamma,
                                                       const float* __restrict__ beta,
                                                       float* __restrict__ out) {
    __shared__ float tile[DD * 9];
    int n0 = blockIdx.x * 8;
    int b = blockIdx.y;
    int tid = threadIdx.x;

    const float* gx = g_xT + (size_t)b * DD * NN + n0;
    for (int idx = tid; idx < DD * 8; idx += 256) {
        int d = idx >> 3;
        int j = idx & 7;
        tile[d * 9 + j] = gx[(size_t)d * NN + j];
    }
    __syncthreads();

    int w = tid >> 5;
    int lane = tid & 31;
    int n = n0 + w;
    const float* xr = x + ((size_t)b * NN + n) * DD;
    float* orow = out + ((size_t)b * NN + n) * DD;

    float y[24];
    float sum = 0.f;
#pragma unroll
    for (int i = 0; i < 24; i++) {
        int d = i * 32 + lane;
        float v = xr[d] + tile[d * 9 + w];
        y[i] = v;
        sum += v;
    }
#pragma unroll
    for (int o = 16; o > 0; o >>= 1) sum += __shfl_xor_sync(0xffffffffu, sum, o);
    float mu = sum * (1.0f / (float)DD);
    float vs = 0.f;
#pragma unroll
    for (int i = 0; i < 24; i++) {
        float d0 = y[i] - mu;
        y[i] = d0;
        vs += d0 * d0;
    }
#pragma unroll
    for (int o = 16; o > 0; o >>= 1) vs += __shfl_xor_sync(0xffffffffu, vs, o);
    float rstd = rsqrtf(vs * (1.0f / (float)DD) + 1e-5f);
#pragma unroll
    for (int i = 0; i < 24; i++) {
        int d = i * 32 + lane;
        orow[d] = y[i] * rstd * gamma[d] + beta[d];
    }
}

// ---------------- launch (single stream; spectral is launch #6 for ncu -s 5) ---------
extern "C" void kernel_launch(void* const* d_in, const int* in_sizes, int n_in,
                              void* d_out, int out_size) {
    const float* x = (const float*)d_in[0];
    const float* bf_g = (const float*)d_in[1];
    const float* bf_l = (const float*)d_in[2];
    const float* mb_g = (const float*)d_in[3];
    const float* mb_l = (const float*)d_in[4];
    const float* w1g = (const float*)d_in[5];
    const float* b1g = (const float*)d_in[6];
    const float* w2g = (const float*)d_in[7];
    const float* b2g = (const float*)d_in[8];
    const float* w1l = (const float*)d_in[9];
    const float* b1l = (const float*)d_in[10];
    const float* w2l = (const float*)d_in[11];
    const float* b2l = (const float*)d_in[12];
    const float* fw = (const float*)d_in[13];
    const float* gamma = (const float*)d_in[14];
    const float* beta = (const float*)d_in[15];
    float* out = (float*)d_out;

    ctx_part_kernel<<<dim3(3, 8, 8), 256>>>(x);                       // 1
    mlp1_part_kernel<<<dim3(144, 8, 2), 128>>>(w1g, w1l);             // 2
    mlp2_part_kernel<<<dim3(98, 8), 128>>>(w2g, w2l, b1g, b1l);       // 3
    mlp2_fin_kernel<<<dim3(98, 8), 128>>>(b2g, b2l);                  // 4
    tr_in_kernel<<<dim3(24, 64, 8), dim3(32, 8)>>>(x);                // 5
    spectral_kernel<<<BD * DD, 256>>>(bf_g, bf_l, mb_g, mb_l, fw);    // 6  <- profiled
    ln_fused_kernel<<<dim3(256, 8), 256>>>(x, gamma, beta, out);      // 7
}

// round 7
// speedup vs baseline: 1.3317x; 1.1080x over previous
#include <cuda_runtime.h>
#include <math.h>

#define BD 8
#define NN 2048
#define DD 768
#define HH 12
#define GBB 1025
#define LBB 9
#define NWW 255
#define HOPP 8
#define NCG (HH * GBB)  // 12300
#define NCL (HH * LBB)  // 108
#define PADI(n) ((n) + ((n) >> 4))

// ---------------- scratch ----------------
__device__ float g_xT[BD * DD * NN];        // (B, D, N), reused for fused output
__device__ float g_ctxp[BD * 64 * DD];
__device__ float g_p1[2 * 24 * BD * DD];
__device__ float g_pg[8 * BD * NCG];
__device__ float g_pl[8 * BD * NCL];
__device__ float g_mg[BD * NCG];
__device__ float g_ml[BD * NCL];
__device__ float2 g_tw[1025];               // exp(-i*pi*k/1024)

__device__ __forceinline__ float2 cmul(float2 a, float2 b) {
    return make_float2(a.x * b.x - a.y * b.y, a.x * b.y + a.y * b.x);
}
__device__ __forceinline__ float2 cadd(float2 a, float2 b) {
    return make_float2(a.x + b.x, a.y + b.y);
}
__device__ __forceinline__ float2 csub(float2 a, float2 b) {
    return make_float2(a.x - b.x, a.y - b.y);
}

// modrelu rescale: max(a+bias,0)/max(a,1e-6) with a=sqrt(m)
__device__ __forceinline__ float mr_scale(float m, float bias) {
    if (m >= 1e-12f) return fmaxf(fmaf(bias, rsqrtf(m), 1.0f), 0.0f);
    return fmaxf(sqrtf(m) + bias, 0.0f) * 1e6f;
}

__device__ __forceinline__ float2 filt_modrelu(float2 v, float pg, float bias) {
    v.x *= pg;
    v.y *= pg;
    float sc = mr_scale(v.x * v.x + v.y * v.y, bias);
    v.x *= sc;
    v.y *= sc;
    return v;
}

// ---------------- twiddle init (also serves as ncu launch-slot filler) ------------
__global__ __launch_bounds__(256) void init_tw_kernel() {
    int k = blockIdx.x * 256 + threadIdx.x;
    if (k <= 1024) {
        float ang = -(float)M_PI * (float)k * (1.0f / 1024.0f);
        float sv, cv;
        sincosf(ang, &sv, &cv);
        g_tw[k] = make_float2(cv, sv);
    }
}

// ---------------- transpose in + ctx partials: x(B,N,D) -> g_xT(B,D,N) ------------
__global__ __launch_bounds__(256) void tr_in_kernel(const float* __restrict__ x) {
    __shared__ float tile[32][33];
    __shared__ float red[8][32];
    int b = blockIdx.z;
    int d0 = blockIdx.x * 32;
    int n0 = blockIdx.y * 32;
    int tx = threadIdx.x, ty = threadIdx.y;

    const float* xp = x + ((size_t)(b * NN + n0 + ty)) * DD + d0 + tx;
    float p = 0.f;
#pragma unroll
    for (int i = 0; i < 4; i++) {
        float v = xp[(size_t)i * 8 * DD];
        tile[ty + 8 * i][tx] = v;
        p += v;
    }
    red[ty][tx] = p;
    __syncthreads();
    if (ty == 0) {
        float s = 0.f;
#pragma unroll
        for (int j = 0; j < 8; j++) s += red[j][tx];
        g_ctxp[(size_t)(b * 64 + blockIdx.y) * DD + d0 + tx] = s;
    }
    float* op = g_xT + ((size_t)(b * DD + d0 + ty)) * NN + n0 + tx;
#pragma unroll
    for (int i = 0; i < 4; i++) op[(size_t)i * 8 * NN] = tile[tx][ty + 8 * i];
}

// ---------------- mlp layer 1 (split-K partials, 64-way ctx reduce folded in) -----
__global__ __launch_bounds__(128) void mlp1_part_kernel(const float* __restrict__ w1g,
                                                        const float* __restrict__ w1l) {
    int cb = blockIdx.x % 6;
    int ks = blockIdx.x / 6;   // 0..23
    int b = blockIdx.y;
    int z = blockIdx.z;
    const float* w = z ? w1l : w1g;
    __shared__ float csp[128];
    __shared__ float cs[32];
    int k0 = ks * 32;
    {
        // 128 threads: 4 threads per k (tid>>5 picks a 16-slice of the 64 partials)
        int kk = threadIdx.x & 31;
        int sl = threadIdx.x >> 5;
        const float* pp = g_ctxp + (size_t)b * 64 * DD + k0 + kk + (size_t)sl * 16 * DD;
        float s = 0.f;
#pragma unroll
        for (int j = 0; j < 16; j++) s += pp[(size_t)j * DD];
        csp[threadIdx.x] = s;
    }
    __syncthreads();
    if (threadIdx.x < 32) {
        float s = csp[threadIdx.x] + csp[threadIdx.x + 32] + csp[threadIdx.x + 64] +
                  csp[threadIdx.x + 96];
        cs[threadIdx.x] = s * (1.0f / (float)NN);
    }
    __syncthreads();
    int c = cb * 128 + threadIdx.x;
    const float* wp = w + (size_t)k0 * DD + c;
    float acc = 0.f;
#pragma unroll 8
    for (int kk = 0; kk < 32; kk++) acc += cs[kk] * wp[(size_t)kk * DD];
    g_p1[((z * 24 + ks) * BD + b) * DD + c] = acc;
}

// ---------------- mlp layer 2 (split-K partials, GELU finish folded in) -----------
__global__ __launch_bounds__(128) void mlp2_part_kernel(const float* __restrict__ w2g,
                                                        const float* __restrict__ w2l,
                                                        const float* __restrict__ b1g,
                                                        const float* __restrict__ b1l) {
    bool isl = (blockIdx.x == 97);
    int by = blockIdx.y;      // k-chunk
    int k0 = by * 96;
    __shared__ float hs[BD * 96];
    const float* bias1 = isl ? b1l : b1g;
    const float* p1 = g_p1 + (isl ? 24 * BD * DD : 0);
    for (int i = threadIdx.x; i < BD * 96; i += 128) {
        int b = i / 96, kk = i - b * 96;
        int k = k0 + kk;
        float s = bias1[k];
#pragma unroll
        for (int ks = 0; ks < 24; ks++) s += p1[(size_t)(ks * BD + b) * DD + k];
        hs[i] = 0.5f * s * (1.0f + erff(s * 0.70710678118654752f));
    }
    __syncthreads();
    int ncol = isl ? NCL : NCG;
    int c = isl ? threadIdx.x : blockIdx.x * 128 + threadIdx.x;
    if (c >= ncol) return;
    const float* w = isl ? w2l : w2g;
    float* pp = isl ? g_pl : g_pg;
    float acc[BD];
#pragma unroll
    for (int b = 0; b < BD; b++) acc[b] = 0.f;
    const float* wp = w + (size_t)k0 * ncol + c;
#pragma unroll 4
    for (int kk = 0; kk < 96; kk++) {
        float wv = wp[(size_t)kk * ncol];
#pragma unroll
        for (int b = 0; b < BD; b++) acc[b] += hs[b * 96 + kk] * wv;
    }
#pragma unroll
    for (int b = 0; b < BD; b++) pp[(size_t)(by * BD + b) * ncol + c] = acc[b];
}

__global__ __launch_bounds__(128) void mlp2_fin_kernel(const float* __restrict__ b2g,
                                                       const float* __restrict__ b2l) {
    bool isl = (blockIdx.x == 97);
    int ncol = isl ? NCL : NCG;
    int c = isl ? threadIdx.x : blockIdx.x * 128 + threadIdx.x;
    if (c >= ncol) return;
    int b = blockIdx.y;
    const float* bias = isl ? b2l : b2g;
    const float* pp = isl ? g_pl : g_pg;
    float* out = isl ? g_ml : g_mg;
    float s = bias[c];
#pragma unroll
    for (int ks = 0; ks < 8; ks++) s += pp[(size_t)(ks * BD + b) * ncol + c];
    out[(size_t)b * ncol + c] = tanhf(s);
}

// ---------------- radix-4 Stockham FFT (1024 pts, 5 stages) ----------------
template <bool INV>
__device__ __forceinline__ void fft1024(float2* src, float2* dst, const float2* tws, int tid) {
#pragma unroll
    for (int t = 0; t < 5; t++) {
        const int s = 1 << (2 * t);
        int q = tid & (s - 1);
        int ps = tid - q;
        float2 a = src[tid];
        float2 b = src[tid + 256];
        float2 c = src[tid + 512];
        float2 d = src[tid + 768];
        float2 w1 = tws[2 * ps];
        float2 w2 = tws[4 * ps];
        if (INV) { w1.y = -w1.y; w2.y = -w2.y; }
        float2 w3 = cmul(w1, w2);
        float2 apc = cadd(a, c);
        float2 amc = csub(a, c);
        float2 bpd = cadd(b, d);
        float2 bmd = csub(b, d);
        int o = 4 * tid - 3 * q;
        dst[o] = cadd(apc, bpd);
        float2 t1, t3;
        if (!INV) {
            t1 = make_float2(amc.x + bmd.y, amc.y - bmd.x);
            t3 = make_float2(amc.x - bmd.y, amc.y + bmd.x);
        } else {
            t1 = make_float2(amc.x - bmd.y, amc.y + bmd.x);
            t3 = make_float2(amc.x + bmd.y, amc.y - bmd.x);
        }
        dst[o + s] = cmul(t1, w1);
        dst[o + 2 * s] = cmul(csub(apc, bpd), w2);
        dst[o + 3 * s] = cmul(t3, w3);
        __syncthreads();
        float2* tmp = src; src = dst; dst = tmp;
    }
}

__global__ __launch_bounds__(256) void spectral_kernel(
    const float* __restrict__ base_g, const float* __restrict__ base_l,
    const float* __restrict__ bias_g, const float* __restrict__ bias_l,
    const float* __restrict__ fusion_w) {
    __shared__ float2 bufA[1024];
    __shared__ float2 uB[1088];        // union: padded s_time (2176 floats) / bufB (1024 float2)
    __shared__ float s_xl[2176];       // padded overlap-add accumulator
    __shared__ float2 tws[1025];
    __shared__ float2 glb[9];          // {0.25*(base+ml), bias} per local freq
    float2* bufB = uB;
    float* s_time = (float*)uB;

    const int tid = threadIdx.x;
    const int blk = blockIdx.x;
    const int b = blk / DD;
    const int c = blk - b * DD;
    const int h = c >> 6;
    const float invs = 0.022097086912079608f;  // 1/sqrt(2048)
    const float r2 = 0.70710678118654752f;

    for (int k = tid; k <= 1024; k += 256) tws[k] = g_tw[k];
    if (tid < 9)
        glb[tid] = make_float2(0.25f * (base_l[h * LBB + tid] + g_ml[(b * HH + h) * LBB + tid]),
                               bias_l[h * LBB + tid]);

    float* row = g_xT + (size_t)blk * NN;
    {
        const float4* src4 = (const float4*)row;
        for (int i = tid; i < 512; i += 256) {
            float4 v = src4[i];
            int p = PADI(4 * i);
            s_time[p] = v.x;
            s_time[p + 1] = v.y;
            s_time[p + 2] = v.z;
            s_time[p + 3] = v.w;
        }
        for (int n = tid; n < 2176; n += 256) s_xl[n] = 0.f;
    }
    __syncthreads();

    // -------- local STFT: single pass, all threads compute; 2-phase overlap-add ------
    {
        const float hq[16] = {0.f, 0.25f * 0.03806023374435663f, 0.25f * 0.14644660940672624f,
                              0.25f * 0.30865828381745508f, 0.25f * 0.5f, 0.25f * 0.69134171618254492f,
                              0.25f * 0.85355339059327376f, 0.25f * 0.96193976625564337f, 0.25f * 1.f,
                              0.25f * 0.96193976625564337f, 0.25f * 0.85355339059327376f,
                              0.25f * 0.69134171618254492f, 0.25f * 0.5f, 0.25f * 0.30865828381745508f,
                              0.25f * 0.14644660940672624f, 0.25f * 0.03806023374435663f};
        const float hw[16] = {0.f, 0.03806023374435663f, 0.14644660940672624f, 0.30865828381745508f,
                              0.5f, 0.69134171618254492f, 0.85355339059327376f, 0.96193976625564337f,
                              1.f, 0.96193976625564337f, 0.85355339059327376f, 0.69134171618254492f,
                              0.5f, 0.30865828381745508f, 0.14644660940672624f, 0.03806023374435663f};
        // w16^k = (cw[k], -sw[k]), k=0..8
        const float cw[9] = {1.f, 0.92387953251128674f, r2, 0.38268343236508977f, 0.f,
                             -0.38268343236508977f, -r2, -0.92387953251128674f, -1.f};
        const float sw[9] = {0.f, 0.38268343236508977f, r2, 0.92387953251128674f, 1.f,
                             0.92387953251128674f, r2, 0.38268343236508977f, 0.f};

        float2 g[8];
        const int nw = tid;
        const int base = nw * HOPP;
        if (nw < NWW) {
            float tw[16];
            tw[0] = 0.f;
#pragma unroll
            for (int j = 1; j < 16; j++) tw[j] = s_time[PADI(base + j)] * hw[j];

            float2 z[8];
#pragma unroll
            for (int m = 0; m < 8; m++) z[m] = make_float2(tw[2 * m], tw[2 * m + 1]);

            // forward FFT8 (DIF), output bit-reversed
            float2 Z[8];
            {
                float2 a0 = cadd(z[0], z[4]), d0 = csub(z[0], z[4]);
                float2 a1 = cadd(z[1], z[5]), d1 = csub(z[1], z[5]);
                float2 a2 = cadd(z[2], z[6]), d2 = csub(z[2], z[6]);
                float2 a3 = cadd(z[3], z[7]), d3 = csub(z[3], z[7]);
                float2 a4 = d0;
                float2 a5 = make_float2(r2 * (d1.x + d1.y), r2 * (d1.y - d1.x));
                float2 a6 = make_float2(d2.y, -d2.x);
                float2 a7 = make_float2(r2 * (d3.y - d3.x), -r2 * (d3.x + d3.y));

                float2 b0 = cadd(a0, a2), b2 = csub(a0, a2);
                float2 b1 = cadd(a1, a3), t13 = csub(a1, a3);
                float2 b3 = make_float2(t13.y, -t13.x);
                float2 b4 = cadd(a4, a6), b6 = csub(a4, a6);
                float2 b5 = cadd(a5, a7), t57 = csub(a5, a7);
                float2 b7 = make_float2(t57.y, -t57.x);

                Z[0] = cadd(b0, b1);
                Z[4] = csub(b0, b1);
                Z[2] = cadd(b2, b3);
                Z[6] = csub(b2, b3);
                Z[1] = cadd(b4, b5);
                Z[5] = csub(b4, b5);
                Z[3] = cadd(b6, b7);
                Z[7] = csub(b6, b7);
            }

            // unpack to rfft16 + filter + modrelu
            float2 X[9];
#pragma unroll
            for (int k = 0; k <= 4; k++) {
                float2 Zk = Z[k];
                float2 Zm = Z[(8 - k) & 7];
                float2 E = make_float2(0.5f * (Zk.x + Zm.x), 0.5f * (Zk.y - Zm.y));
                float2 O = make_float2(0.5f * (Zk.y + Zm.y), -0.5f * (Zk.x - Zm.x));
                float2 w = make_float2(cw[k], -sw[k]);
                float2 Xk = cadd(E, cmul(w, O));
                float2 gb = glb[k];
                X[k] = filt_modrelu(Xk, gb.x, gb.y);
                if (k > 0 && k < 4) {
                    int kk = 8 - k;
                    float2 wm = make_float2(cw[kk], -sw[kk]);
                    float2 Xm = cadd(make_float2(E.x, -E.y), cmul(wm, make_float2(O.x, -O.y)));
                    float2 gb2 = glb[kk];
                    X[kk] = filt_modrelu(Xm, gb2.x, gb2.y);
                } else if (k == 0) {
                    float2 Xm = make_float2(E.x - O.x, O.y - E.y);
                    float2 gb2 = glb[8];
                    X[8] = filt_modrelu(Xm, gb2.x, gb2.y);
                }
            }

            // repack: G[m] = S + i*conj(w16^m)*D
            float2 G[8];
#pragma unroll
            for (int m = 0; m < 8; m++) {
                float2 Xa = X[m];
                float2 Xb = X[8 - m];
                float2 S = make_float2(Xa.x + Xb.x, Xa.y - Xb.y);
                float2 D = make_float2(Xa.x - Xb.x, Xa.y + Xb.y);
                float2 wc = make_float2(cw[m], sw[m]);
                float2 t = cmul(wc, D);
                G[m] = make_float2(S.x - t.y, S.y + t.x);
            }

            // inverse FFT8 (conjugate twiddles), output bit-reversed
            {
                float2 a0 = cadd(G[0], G[4]), d0 = csub(G[0], G[4]);
                float2 a1 = cadd(G[1], G[5]), d1 = csub(G[1], G[5]);
                float2 a2 = cadd(G[2], G[6]), d2 = csub(G[2], G[6]);
                float2 a3 = cadd(G[3], G[7]), d3 = csub(G[3], G[7]);
                float2 a4 = d0;
                float2 a5 = make_float2(r2 * (d1.x - d1.y), r2 * (d1.x + d1.y));
                float2 a6 = make_float2(-d2.y, d2.x);
                float2 a7 = make_float2(-r2 * (d3.x + d3.y), r2 * (d3.x - d3.y));

                float2 b0 = cadd(a0, a2), b2 = csub(a0, a2);
                float2 b1 = cadd(a1, a3), t13 = csub(a1, a3);
                float2 b3 = make_float2(-t13.y, t13.x);
                float2 b4 = cadd(a4, a6), b6 = csub(a4, a6);
                float2 b5 = cadd(a5, a7), t57 = csub(a5, a7);
                float2 b7 = make_float2(-t57.y, t57.x);

                g[0] = cadd(b0, b1);
                g[4] = csub(b0, b1);
                g[2] = cadd(b2, b3);
                g[6] = csub(b2, b3);
                g[1] = cadd(b4, b5);
                g[5] = csub(b4, b5);
                g[3] = cadd(b6, b7);
                g[7] = csub(b6, b7);
            }
        }
        __syncthreads();

        // 2-phase overlap-add: even windows disjoint, odd windows disjoint
        if (nw < NWW && !(nw & 1)) {
#pragma unroll
            for (int m = 0; m < 8; m++) {
                if (m > 0) s_xl[PADI(base + 2 * m)] += g[m].x * hq[2 * m];
                s_xl[PADI(base + 2 * m + 1)] += g[m].y * hq[2 * m + 1];
            }
        }
        __syncthreads();
        if (nw < NWW && (nw & 1)) {
#pragma unroll
            for (int m = 0; m < 8; m++) {
                if (m > 0) s_xl[PADI(base + 2 * m)] += g[m].x * hq[2 * m];
                s_xl[PADI(base + 2 * m + 1)] += g[m].y * hq[2 * m + 1];
            }
        }
        __syncthreads();
    }

    // -------- global path --------
    for (int m = tid; m < 1024; m += 256) {
        int p = PADI(2 * m);
        bufA[m] = make_float2(s_time[p], s_time[p + 1]);
    }
    __syncthreads();

    fft1024<false>(bufA, bufB, tws, tid);  // result in bufB

    // merged: unpack Z -> X -> filter/modrelu -> repack G (bufA)
    {
        const float* mgb = g_mg + (b * HH + h) * GBB;
        const float* bgb = base_g + h * GBB;
        const float* bib = bias_g + h * GBB;
        float2* Z = bufB;
        float2* G = bufA;
        for (int k = tid; k <= 512; k += 256) {
            float2 Zk = Z[k & 1023];
            float2 Zm = Z[(1024 - k) & 1023];
            float2 E = make_float2(0.5f * (Zk.x + Zm.x), 0.5f * (Zk.y - Zm.y));
            float2 O = make_float2(0.5f * (Zk.y + Zm.y), -0.5f * (Zk.x - Zm.x));
            float2 Xk = cadd(E, cmul(tws[k], O));
            Xk = filt_modrelu(Xk, invs * (bgb[k] + mgb[k]), bib[k]);
            float2 Xm;
            if (k < 512) {
                int kk = 1024 - k;
                Xm = cadd(make_float2(E.x, -E.y), cmul(tws[kk], make_float2(O.x, -O.y)));
                Xm = filt_modrelu(Xm, invs * (bgb[kk] + mgb[kk]), bib[kk]);
            } else {
                Xm = Xk;
            }
            {
                float2 S = make_float2(Xk.x + Xm.x, Xk.y - Xm.y);
                float2 Dd = make_float2(Xk.x - Xm.x, Xk.y + Xm.y);
                float2 wc = make_float2(tws[k].x, -tws[k].y);
                float2 t = cmul(wc, Dd);
                G[k] = make_float2(S.x - t.y, S.y + t.x);
            }
            if (k > 0 && k < 512) {
                int jj = 1024 - k;
                float2 S = make_float2(Xm.x + Xk.x, Xm.y - Xk.y);
                float2 Dd = make_float2(Xm.x - Xk.x, Xm.y + Xk.y);
                float2 wc = make_float2(tws[jj].x, -tws[jj].y);
                float2 t = cmul(wc, Dd);
                G[jj] = make_float2(S.x - t.y, S.y + t.x);
            }
        }
    }
    __syncthreads();

    fft1024<true>(bufA, bufB, tws, tid);  // inverse: result in bufB

    // fuse + contiguous write back into g_xT
    {
        float fw0 = fusion_w[0];
        float fw1 = fusion_w[1];
        float2* orow2 = (float2*)row;
        for (int m = tid; m < 1024; m += 256) {
            float2 zc = bufB[m];
            int p = PADI(2 * m);
            orow2[m] = make_float2(fw0 * (zc.x * invs) + fw1 * s_xl[p],
                                   fw0 * (zc.y * invs) + fw1 * s_xl[p + 1]);
        }
    }
}

// ---------------- fused transpose-out + residual + layernorm ----------------
__global__ __launch_bounds__(256) void ln_fused_kernel(const float* __restrict__ x,
                                                       const float* __restrict__ gamma,
                                                       const float* __restrict__ beta,
                                                       float* __restrict__ out) {
    __shared__ float tile[DD * 9];
    int n0 = blockIdx.x * 8;
    int b = blockIdx.y;
    int tid = threadIdx.x;

    const float* gx = g_xT + (size_t)b * DD * NN + n0;
    for (int idx = tid; idx < DD * 8; idx += 256) {
        int d = idx >> 3;
        int j = idx & 7;
        tile[d * 9 + j] = gx[(size_t)d * NN + j];
    }
    __syncthreads();

    int w = tid >> 5;
    int lane = tid & 31;
    int n = n0 + w;
    const float* xr = x + ((size_t)b * NN + n) * DD;
    float* orow = out + ((size_t)b * NN + n) * DD;

    float y[24];
    float sum = 0.f;
#pragma unroll
    for (int i = 0; i < 24; i++) {
        int d = i * 32 + lane;
        float v = xr[d] + tile[d * 9 + w];
        y[i] = v;
        sum += v;
    }
#pragma unroll
    for (int o = 16; o > 0; o >>= 1) sum += __shfl_xor_sync(0xffffffffu, sum, o);
    float mu = sum * (1.0f / (float)DD);
    float vs = 0.f;
#pragma unroll
    for (int i = 0; i < 24; i++) {
        float d0 = y[i] - mu;
        y[i] = d0;
        vs += d0 * d0;
    }
#pragma unroll
    for (int o = 16; o > 0; o >>= 1) vs += __shfl_xor_sync(0xffffffffu, vs, o);
    float rstd = rsqrtf(vs * (1.0f / (float)DD) + 1e-5f);
#pragma unroll
    for (int i = 0; i < 24; i++) {
        int d = i * 32 + lane;
        orow[d] = y[i] * rstd * gamma[d] + beta[d];
    }
}

// ---------------- launch (spectral is launch #6 for ncu -s 5) ---------
extern "C" void kernel_launch(void* const* d_in, const int* in_sizes, int n_in,
                              void* d_out, int out_size) {
    const float* x = (const float*)d_in[0];
    const float* bf_g = (const float*)d_in[1];
    const float* bf_l = (const float*)d_in[2];
    const float* mb_g = (const float*)d_in[3];
    const float* mb_l = (const float*)d_in[4];
    const float* w1g = (const float*)d_in[5];
    const float* b1g = (const float*)d_in[6];
    const float* w2g = (const float*)d_in[7];
    const float* b2g = (const float*)d_in[8];
    const float* w1l = (const float*)d_in[9];
    const float* b1l = (const float*)d_in[10];
    const float* w2l = (const float*)d_in[11];
    const float* b2l = (const float*)d_in[12];
    const float* fw = (const float*)d_in[13];
    const float* gamma = (const float*)d_in[14];
    const float* beta = (const float*)d_in[15];
    float* out = (float*)d_out;

    tr_in_kernel<<<dim3(24, 64, 8), dim3(32, 8)>>>(x);                // 1
    mlp1_part_kernel<<<dim3(144, 8, 2), 128>>>(w1g, w1l);             // 2
    mlp2_part_kernel<<<dim3(98, 8), 128>>>(w2g, w2l, b1g, b1l);       // 3
    mlp2_fin_kernel<<<dim3(98, 8), 128>>>(b2g, b2l);                  // 4
    init_tw_kernel<<<5, 256>>>();                                     // 5
    spectral_kernel<<<BD * DD, 256>>>(bf_g, bf_l, mb_g, mb_l, fw);    // 6  <- profiled
    ln_fused_kernel<<<dim3(256, 8), 256>>>(x, gamma, beta, out);      // 7
}

// round 8
// speedup vs baseline: 1.4058x; 1.0556x over previous
#include <cuda_runtime.h>
#include <math.h>

#define BD 8
#define NN 2048
#define DD 768
#define HH 12
#define GBB 1025
#define LBB 9
#define NWW 255
#define HOPP 8
#define NCG (HH * GBB)  // 12300
#define NCL (HH * LBB)  // 108
#define PADI(n) ((n) + ((n) >> 4))

// ---------------- scratch ----------------
__device__ float g_xT[BD * DD * NN];        // (B, D, N), reused for fused output
__device__ float g_ctxp[BD * 64 * DD];
__device__ float g_p1[2 * 24 * BD * DD];
__device__ float g_pg[8 * BD * NCG];
__device__ float g_pl[8 * BD * NCL];
__device__ float g_mg[BD * NCG];
__device__ float g_ml[BD * NCL];
__device__ float2 g_tw[1025];               // exp(-i*pi*k/1024)

__device__ __forceinline__ float2 cmul(float2 a, float2 b) {
    return make_float2(a.x * b.x - a.y * b.y, a.x * b.y + a.y * b.x);
}
__device__ __forceinline__ float2 cadd(float2 a, float2 b) {
    return make_float2(a.x + b.x, a.y + b.y);
}
__device__ __forceinline__ float2 csub(float2 a, float2 b) {
    return make_float2(a.x - b.x, a.y - b.y);
}

// modrelu rescale: max(a+bias,0)/max(a,1e-6) with a=sqrt(m)
__device__ __forceinline__ float mr_scale(float m, float bias) {
    if (m >= 1e-12f) return fmaxf(fmaf(bias, rsqrtf(m), 1.0f), 0.0f);
    return fmaxf(sqrtf(m) + bias, 0.0f) * 1e6f;
}

__device__ __forceinline__ float2 filt_modrelu(float2 v, float pg, float bias) {
    v.x *= pg;
    v.y *= pg;
    float sc = mr_scale(v.x * v.x + v.y * v.y, bias);
    v.x *= sc;
    v.y *= sc;
    return v;
}

// ---------------- twiddle init ----------------
__global__ __launch_bounds__(256) void init_tw_kernel() {
    int k = blockIdx.x * 256 + threadIdx.x;
    if (k <= 1024) {
        float ang = -(float)M_PI * (float)k * (1.0f / 1024.0f);
        float sv, cv;
        sincosf(ang, &sv, &cv);
        g_tw[k] = make_float2(cv, sv);
    }
}

// ---------------- transpose in + ctx partials: x(B,N,D) -> g_xT(B,D,N) ------------
__global__ __launch_bounds__(256) void tr_in_kernel(const float* __restrict__ x) {
    __shared__ float tile[32][33];
    __shared__ float red[8][32];
    int b = blockIdx.z;
    int d0 = blockIdx.x * 32;
    int n0 = blockIdx.y * 32;
    int tx = threadIdx.x, ty = threadIdx.y;

    const float* xp = x + ((size_t)(b * NN + n0 + ty)) * DD + d0 + tx;
    float p = 0.f;
#pragma unroll
    for (int i = 0; i < 4; i++) {
        float v = xp[(size_t)i * 8 * DD];
        tile[ty + 8 * i][tx] = v;
        p += v;
    }
    red[ty][tx] = p;
    __syncthreads();
    if (ty == 0) {
        float s = 0.f;
#pragma unroll
        for (int j = 0; j < 8; j++) s += red[j][tx];
        g_ctxp[(size_t)(b * 64 + blockIdx.y) * DD + d0 + tx] = s;
    }
    float* op = g_xT + ((size_t)(b * DD + d0 + ty)) * NN + n0 + tx;
#pragma unroll
    for (int i = 0; i < 4; i++) op[(size_t)i * 8 * NN] = tile[tx][ty + 8 * i];
}

// ---------------- mlp layer 1 (split-K partials, 64-way ctx reduce folded in) -----
__global__ __launch_bounds__(128) void mlp1_part_kernel(const float* __restrict__ w1g,
                                                        const float* __restrict__ w1l) {
    int cb = blockIdx.x % 6;
    int ks = blockIdx.x / 6;   // 0..23
    int b = blockIdx.y;
    int z = blockIdx.z;
    const float* w = z ? w1l : w1g;
    __shared__ float csp[128];
    __shared__ float cs[32];
    int k0 = ks * 32;
    {
        int kk = threadIdx.x & 31;
        int sl = threadIdx.x >> 5;
        const float* pp = g_ctxp + (size_t)b * 64 * DD + k0 + kk + (size_t)sl * 16 * DD;
        float s = 0.f;
#pragma unroll
        for (int j = 0; j < 16; j++) s += pp[(size_t)j * DD];
        csp[threadIdx.x] = s;
    }
    __syncthreads();
    if (threadIdx.x < 32) {
        float s = csp[threadIdx.x] + csp[threadIdx.x + 32] + csp[threadIdx.x + 64] +
                  csp[threadIdx.x + 96];
        cs[threadIdx.x] = s * (1.0f / (float)NN);
    }
    __syncthreads();
    int c = cb * 128 + threadIdx.x;
    const float* wp = w + (size_t)k0 * DD + c;
    float acc = 0.f;
#pragma unroll 8
    for (int kk = 0; kk < 32; kk++) acc += cs[kk] * wp[(size_t)kk * DD];
    g_p1[((z * 24 + ks) * BD + b) * DD + c] = acc;
}

// ---------------- mlp layer 2 (split-K partials, GELU finish folded in) -----------
__global__ __launch_bounds__(128) void mlp2_part_kernel(const float* __restrict__ w2g,
                                                        const float* __restrict__ w2l,
                                                        const float* __restrict__ b1g,
                                                        const float* __restrict__ b1l) {
    bool isl = (blockIdx.x == 97);
    int by = blockIdx.y;      // k-chunk
    int k0 = by * 96;
    __shared__ float hs[BD * 96];
    const float* bias1 = isl ? b1l : b1g;
    const float* p1 = g_p1 + (isl ? 24 * BD * DD : 0);
    for (int i = threadIdx.x; i < BD * 96; i += 128) {
        int b = i / 96, kk = i - b * 96;
        int k = k0 + kk;
        float s = bias1[k];
#pragma unroll
        for (int ks = 0; ks < 24; ks++) s += p1[(size_t)(ks * BD + b) * DD + k];
        hs[i] = 0.5f * s * (1.0f + erff(s * 0.70710678118654752f));
    }
    __syncthreads();
    int ncol = isl ? NCL : NCG;
    int c = isl ? threadIdx.x : blockIdx.x * 128 + threadIdx.x;
    if (c >= ncol) return;
    const float* w = isl ? w2l : w2g;
    float* pp = isl ? g_pl : g_pg;
    float acc[BD];
#pragma unroll
    for (int b = 0; b < BD; b++) acc[b] = 0.f;
    const float* wp = w + (size_t)k0 * ncol + c;
#pragma unroll 4
    for (int kk = 0; kk < 96; kk++) {
        float wv = wp[(size_t)kk * ncol];
#pragma unroll
        for (int b = 0; b < BD; b++) acc[b] += hs[b * 96 + kk] * wv;
    }
#pragma unroll
    for (int b = 0; b < BD; b++) pp[(size_t)(by * BD + b) * ncol + c] = acc[b];
}

__global__ __launch_bounds__(128) void mlp2_fin_kernel(const float* __restrict__ b2g,
                                                       const float* __restrict__ b2l) {
    bool isl = (blockIdx.x == 97);
    int ncol = isl ? NCL : NCG;
    int c = isl ? threadIdx.x : blockIdx.x * 128 + threadIdx.x;
    if (c >= ncol) return;
    int b = blockIdx.y;
    const float* bias = isl ? b2l : b2g;
    const float* pp = isl ? g_pl : g_pg;
    float* out = isl ? g_ml : g_mg;
    float s = bias[c];
#pragma unroll
    for (int ks = 0; ks < 8; ks++) s += pp[(size_t)(ks * BD + b) * ncol + c];
    out[(size_t)b * ncol + c] = tanhf(s);
}

// ---------------- generic radix-4 Stockham stage (twiddle via __ldg, w2=w1^2) -----
template <bool INV>
__device__ __forceinline__ void fstage(const float2* __restrict__ src,
                                       float2* __restrict__ dst, int t, int tid) {
    const int s = 1 << (2 * t);
    int q = tid & (s - 1);
    int ps = tid - q;
    float2 a = src[tid];
    float2 b = src[tid + 256];
    float2 c = src[tid + 512];
    float2 d = src[tid + 768];
    float2 w1 = __ldg(&g_tw[2 * ps]);
    if (INV) w1.y = -w1.y;
    float2 w2 = cmul(w1, w1);
    float2 w3 = cmul(w1, w2);
    float2 apc = cadd(a, c);
    float2 amc = csub(a, c);
    float2 bpd = cadd(b, d);
    float2 bmd = csub(b, d);
    int o = 4 * tid - 3 * q;
    dst[o] = cadd(apc, bpd);
    float2 t1, t3;
    if (!INV) {
        t1 = make_float2(amc.x + bmd.y, amc.y - bmd.x);
        t3 = make_float2(amc.x - bmd.y, amc.y + bmd.x);
    } else {
        t1 = make_float2(amc.x - bmd.y, amc.y + bmd.x);
        t3 = make_float2(amc.x + bmd.y, amc.y - bmd.x);
    }
    dst[o + s] = cmul(t1, w1);
    dst[o + 2 * s] = cmul(csub(apc, bpd), w2);
    dst[o + 3 * s] = cmul(t3, w3);
}

__global__ __launch_bounds__(256) void spectral_kernel(
    const float* __restrict__ base_g, const float* __restrict__ base_l,
    const float* __restrict__ bias_g, const float* __restrict__ bias_l,
    const float* __restrict__ fusion_w) {
    __shared__ float2 uA[1088];        // union: padded s_time (2176 floats) / bufA
    __shared__ float2 bufB[1024];
    __shared__ float s_xl[2176];       // padded overlap-add accumulator
    __shared__ float2 glb[9];          // {0.25*(base+ml), bias} per local freq
    float2* bufA = uA;
    float* s_time = (float*)uA;

    const int tid = threadIdx.x;
    const int blk = blockIdx.x;
    const int b = blk / DD;
    const int c = blk - b * DD;
    const int h = c >> 6;
    const float invs = 0.022097086912079608f;  // 1/sqrt(2048)
    const float r2 = 0.70710678118654752f;

    if (tid < 9)
        glb[tid] = make_float2(0.25f * (base_l[h * LBB + tid] + g_ml[(b * HH + h) * LBB + tid]),
                               bias_l[h * LBB + tid]);

    float* row = g_xT + (size_t)blk * NN;
    {
        const float4* src4 = (const float4*)row;
        for (int i = tid; i < 512; i += 256) {
            float4 v = src4[i];
            int p = PADI(4 * i);
            s_time[p] = v.x;
            s_time[p + 1] = v.y;
            s_time[p + 2] = v.z;
            s_time[p + 3] = v.w;
        }
        for (int n = tid; n < 2176; n += 256) s_xl[n] = 0.f;
    }
    __syncthreads();

    // -------- local STFT: single pass, all threads compute; 2-phase overlap-add ------
    {
        const float hq[16] = {0.f, 0.25f * 0.03806023374435663f, 0.25f * 0.14644660940672624f,
                              0.25f * 0.30865828381745508f, 0.25f * 0.5f, 0.25f * 0.69134171618254492f,
                              0.25f * 0.85355339059327376f, 0.25f * 0.96193976625564337f, 0.25f * 1.f,
                              0.25f * 0.96193976625564337f, 0.25f * 0.85355339059327376f,
                              0.25f * 0.69134171618254492f, 0.25f * 0.5f, 0.25f * 0.30865828381745508f,
                              0.25f * 0.14644660940672624f, 0.25f * 0.03806023374435663f};
        const float hw[16] = {0.f, 0.03806023374435663f, 0.14644660940672624f, 0.30865828381745508f,
                              0.5f, 0.69134171618254492f, 0.85355339059327376f, 0.96193976625564337f,
                              1.f, 0.96193976625564337f, 0.85355339059327376f, 0.69134171618254492f,
                              0.5f, 0.30865828381745508f, 0.14644660940672624f, 0.03806023374435663f};
        const float cw[9] = {1.f, 0.92387953251128674f, r2, 0.38268343236508977f, 0.f,
                             -0.38268343236508977f, -r2, -0.92387953251128674f, -1.f};
        const float sw[9] = {0.f, 0.38268343236508977f, r2, 0.92387953251128674f, 1.f,
                             0.92387953251128674f, r2, 0.38268343236508977f, 0.f};

        float2 g[8];
        const int nw = tid;
        const int base = nw * HOPP;
        if (nw < NWW) {
            float tw[16];
            tw[0] = 0.f;
#pragma unroll
            for (int j = 1; j < 16; j++) tw[j] = s_time[PADI(base + j)] * hw[j];

            float2 z[8];
#pragma unroll
            for (int m = 0; m < 8; m++) z[m] = make_float2(tw[2 * m], tw[2 * m + 1]);

            // forward FFT8 (DIF), output bit-reversed
            float2 Z[8];
            {
                float2 a0 = cadd(z[0], z[4]), d0 = csub(z[0], z[4]);
                float2 a1 = cadd(z[1], z[5]), d1 = csub(z[1], z[5]);
                float2 a2 = cadd(z[2], z[6]), d2 = csub(z[2], z[6]);
                float2 a3 = cadd(z[3], z[7]), d3 = csub(z[3], z[7]);
                float2 a4 = d0;
                float2 a5 = make_float2(r2 * (d1.x + d1.y), r2 * (d1.y - d1.x));
                float2 a6 = make_float2(d2.y, -d2.x);
                float2 a7 = make_float2(r2 * (d3.y - d3.x), -r2 * (d3.x + d3.y));

                float2 b0 = cadd(a0, a2), b2 = csub(a0, a2);
                float2 b1 = cadd(a1, a3), t13 = csub(a1, a3);
                float2 b3 = make_float2(t13.y, -t13.x);
                float2 b4 = cadd(a4, a6), b6 = csub(a4, a6);
                float2 b5 = cadd(a5, a7), t57 = csub(a5, a7);
                float2 b7 = make_float2(t57.y, -t57.x);

                Z[0] = cadd(b0, b1);
                Z[4] = csub(b0, b1);
                Z[2] = cadd(b2, b3);
                Z[6] = csub(b2, b3);
                Z[1] = cadd(b4, b5);
                Z[5] = csub(b4, b5);
                Z[3] = cadd(b6, b7);
                Z[7] = csub(b6, b7);
            }

            // unpack to rfft16 + filter + modrelu
            float2 X[9];
#pragma unroll
            for (int k = 0; k <= 4; k++) {
                float2 Zk = Z[k];
                float2 Zm = Z[(8 - k) & 7];
                float2 E = make_float2(0.5f * (Zk.x + Zm.x), 0.5f * (Zk.y - Zm.y));
                float2 O = make_float2(0.5f * (Zk.y + Zm.y), -0.5f * (Zk.x - Zm.x));
                float2 w = make_float2(cw[k], -sw[k]);
                float2 Xk = cadd(E, cmul(w, O));
                float2 gb = glb[k];
                X[k] = filt_modrelu(Xk, gb.x, gb.y);
                if (k > 0 && k < 4) {
                    int kk = 8 - k;
                    float2 wm = make_float2(cw[kk], -sw[kk]);
                    float2 Xm = cadd(make_float2(E.x, -E.y), cmul(wm, make_float2(O.x, -O.y)));
                    float2 gb2 = glb[kk];
                    X[kk] = filt_modrelu(Xm, gb2.x, gb2.y);
                } else if (k == 0) {
                    float2 Xm = make_float2(E.x - O.x, O.y - E.y);
                    float2 gb2 = glb[8];
                    X[8] = filt_modrelu(Xm, gb2.x, gb2.y);
                }
            }

            // repack: G[m] = S + i*conj(w16^m)*D
            float2 G[8];
#pragma unroll
            for (int m = 0; m < 8; m++) {
                float2 Xa = X[m];
                float2 Xb = X[8 - m];
                float2 S = make_float2(Xa.x + Xb.x, Xa.y - Xb.y);
                float2 D = make_float2(Xa.x - Xb.x, Xa.y + Xb.y);
                float2 wc = make_float2(cw[m], sw[m]);
                float2 t = cmul(wc, D);
                G[m] = make_float2(S.x - t.y, S.y + t.x);
            }

            // inverse FFT8 (conjugate twiddles), output bit-reversed
            {
                float2 a0 = cadd(G[0], G[4]), d0 = csub(G[0], G[4]);
                float2 a1 = cadd(G[1], G[5]), d1 = csub(G[1], G[5]);
                float2 a2 = cadd(G[2], G[6]), d2 = csub(G[2], G[6]);
                float2 a3 = cadd(G[3], G[7]), d3 = csub(G[3], G[7]);
                float2 a4 = d0;
                float2 a5 = make_float2(r2 * (d1.x - d1.y), r2 * (d1.x + d1.y));
                float2 a6 = make_float2(-d2.y, d2.x);
                float2 a7 = make_float2(-r2 * (d3.x + d3.y), r2 * (d3.x - d3.y));

                float2 b0 = cadd(a0, a2), b2 = csub(a0, a2);
                float2 b1 = cadd(a1, a3), t13 = csub(a1, a3);
                float2 b3 = make_float2(-t13.y, t13.x);
                float2 b4 = cadd(a4, a6), b6 = csub(a4, a6);
                float2 b5 = cadd(a5, a7), t57 = csub(a5, a7);
                float2 b7 = make_float2(-t57.y, t57.x);

                g[0] = cadd(b0, b1);
                g[4] = csub(b0, b1);
                g[2] = cadd(b2, b3);
                g[6] = csub(b2, b3);
                g[1] = cadd(b4, b5);
                g[5] = csub(b4, b5);
                g[3] = cadd(b6, b7);
                g[7] = csub(b6, b7);
            }
        }
        __syncthreads();

        // 2-phase overlap-add: even windows disjoint, odd windows disjoint
        if (nw < NWW && !(nw & 1)) {
#pragma unroll
            for (int m = 0; m < 8; m++) {
                if (m > 0) s_xl[PADI(base + 2 * m)] += g[m].x * hq[2 * m];
                s_xl[PADI(base + 2 * m + 1)] += g[m].y * hq[2 * m + 1];
            }
        }
        __syncthreads();
        if (nw < NWW && (nw & 1)) {
#pragma unroll
            for (int m = 0; m < 8; m++) {
                if (m > 0) s_xl[PADI(base + 2 * m)] += g[m].x * hq[2 * m];
                s_xl[PADI(base + 2 * m + 1)] += g[m].y * hq[2 * m + 1];
            }
        }
        __syncthreads();
    }

    // -------- global path: forward FFT, stage 0 reads packed padded s_time ---------
    {
        float2 a = make_float2(s_time[PADI(2 * tid)], s_time[PADI(2 * tid + 1)]);
        float2 bb = make_float2(s_time[PADI(2 * (tid + 256))], s_time[PADI(2 * (tid + 256) + 1)]);
        float2 cc = make_float2(s_time[PADI(2 * (tid + 512))], s_time[PADI(2 * (tid + 512) + 1)]);
        float2 dd = make_float2(s_time[PADI(2 * (tid + 768))], s_time[PADI(2 * (tid + 768) + 1)]);
        float2 w1 = __ldg(&g_tw[2 * tid]);
        float2 w2 = cmul(w1, w1);
        float2 w3 = cmul(w1, w2);
        float2 apc = cadd(a, cc);
        float2 amc = csub(a, cc);
        float2 bpd = cadd(bb, dd);
        float2 bmd = csub(bb, dd);
        int o = 4 * tid;
        bufB[o] = cadd(apc, bpd);
        float2 t1 = make_float2(amc.x + bmd.y, amc.y - bmd.x);
        float2 t3 = make_float2(amc.x - bmd.y, amc.y + bmd.x);
        bufB[o + 1] = cmul(t1, w1);
        bufB[o + 2] = cmul(csub(apc, bpd), w2);
        bufB[o + 3] = cmul(t3, w3);
    }
    __syncthreads();
    // stages 1..4: B->A->B->A->B
    {
        float2* src = bufB;
        float2* dst = bufA;
#pragma unroll
        for (int t = 1; t < 5; t++) {
            fstage<false>(src, dst, t, tid);
            __syncthreads();
            float2* tmp = src; src = dst; dst = tmp;
        }
    }
    // Z in bufB. merged: unpack -> filter/modrelu -> repack G into bufA
    {
        const float* mgb = g_mg + (b * HH + h) * GBB;
        const float* bgb = base_g + h * GBB;
        const float* bib = bias_g + h * GBB;
        float2* Z = bufB;
        float2* G = bufA;
        for (int k = tid; k <= 512; k += 256) {
            float2 Zk = Z[k & 1023];
            float2 Zm = Z[(1024 - k) & 1023];
            float2 tk = __ldg(&g_tw[k]);   // k <= 512
            float2 E = make_float2(0.5f * (Zk.x + Zm.x), 0.5f * (Zk.y - Zm.y));
            float2 O = make_float2(0.5f * (Zk.y + Zm.y), -0.5f * (Zk.x - Zm.x));
            float2 Xk = cadd(E, cmul(tk, O));
            Xk = filt_modrelu(Xk, invs * (bgb[k] + mgb[k]), bib[k]);
            float2 Xm;
            if (k < 512) {
                int kk = 1024 - k;
                // tws[kk] = -conj(tk)
                float2 tkk = make_float2(-tk.x, tk.y);
                Xm = cadd(make_float2(E.x, -E.y), cmul(tkk, make_float2(O.x, -O.y)));
                Xm = filt_modrelu(Xm, invs * (bgb[kk] + mgb[kk]), bib[kk]);
            } else {
                Xm = Xk;
            }
            {
                float2 S = make_float2(Xk.x + Xm.x, Xk.y - Xm.y);
                float2 Dd = make_float2(Xk.x - Xm.x, Xk.y + Xm.y);
                float2 wc = make_float2(tk.x, -tk.y);   // conj(tws[k])
                float2 t = cmul(wc, Dd);
                G[k] = make_float2(S.x - t.y, S.y + t.x);
            }
            if (k > 0 && k < 512) {
                int jj = 1024 - k;
                float2 S = make_float2(Xm.x + Xk.x, Xm.y - Xk.y);
                float2 Dd = make_float2(Xm.x - Xk.x, Xm.y + Xk.y);
                float2 wc = make_float2(-tk.x, -tk.y);  // conj(tws[jj]) = -tk
                float2 t = cmul(wc, Dd);
                G[jj] = make_float2(S.x - t.y, S.y + t.x);
            }
        }
    }
    __syncthreads();

    // inverse FFT: stages 0..3 (A->B->A->B->A), final stage fused with global store
    {
        float2* src = bufA;
        float2* dst = bufB;
#pragma unroll
        for (int t = 0; t < 4; t++) {
            fstage<true>(src, dst, t, tid);
            __syncthreads();
            float2* tmp = src; src = dst; dst = tmp;
        }
        // src == bufA. final stage: s=256, ps=0 -> unit twiddles; fuse + store
        float fw0 = fusion_w[0] * invs;
        float fw1 = fusion_w[1];
        float2* orow2 = (float2*)row;
        float2 a = src[tid];
        float2 bb = src[tid + 256];
        float2 cc = src[tid + 512];
        float2 dd = src[tid + 768];
        float2 apc = cadd(a, cc);
        float2 amc = csub(a, cc);
        float2 bpd = cadd(bb, dd);
        float2 bmd = csub(bb, dd);
        float2 v0 = cadd(apc, bpd);                              // m = tid
        float2 v1 = make_float2(amc.x - bmd.y, amc.y + bmd.x);   // m = tid+256
        float2 v2 = csub(apc, bpd);                              // m = tid+512
        float2 v3 = make_float2(amc.x + bmd.y, amc.y - bmd.x);   // m = tid+768
        int m0 = tid, m1 = tid + 256, m2 = tid + 512, m3 = tid + 768;
        orow2[m0] = make_float2(fw0 * v0.x + fw1 * s_xl[PADI(2 * m0)],
                                fw0 * v0.y + fw1 * s_xl[PADI(2 * m0 + 1)]);
        orow2[m1] = make_float2(fw0 * v1.x + fw1 * s_xl[PADI(2 * m1)],
                                fw0 * v1.y + fw1 * s_xl[PADI(2 * m1 + 1)]);
        orow2[m2] = make_float2(fw0 * v2.x + fw1 * s_xl[PADI(2 * m2)],
                                fw0 * v2.y + fw1 * s_xl[PADI(2 * m2 + 1)]);
        orow2[m3] = make_float2(fw0 * v3.x + fw1 * s_xl[PADI(2 * m3)],
                                fw0 * v3.y + fw1 * s_xl[PADI(2 * m3 + 1)]);
    }
}

// ---------------- fused transpose-out + residual + layernorm ----------------
__global__ __launch_bounds__(256) void ln_fused_kernel(const float* __restrict__ x,
                                                       const float* __restrict__ gamma,
                                                       const float* __restrict__ beta,
                                                       float* __restrict__ out) {
    __shared__ float tile[DD * 9];
    int n0 = blockIdx.x * 8;
    int b = blockIdx.y;
    int tid = threadIdx.x;

    const float* gx = g_xT + (size_t)b * DD * NN + n0;
    for (int idx = tid; idx < DD * 8; idx += 256) {
        int d = idx >> 3;
        int j = idx & 7;
        tile[d * 9 + j] = gx[(size_t)d * NN + j];
    }
    __syncthreads();

    int w = tid >> 5;
    int lane = tid & 31;
    int n = n0 + w;
    const float* xr = x + ((size_t)b * NN + n) * DD;
    float* orow = out + ((size_t)b * NN + n) * DD;

    float y[24];
    float sum = 0.f;
#pragma unroll
    for (int i = 0; i < 24; i++) {
        int d = i * 32 + lane;
        float v = xr[d] + tile[d * 9 + w];
        y[i] = v;
        sum += v;
    }
#pragma unroll
    for (int o = 16; o > 0; o >>= 1) sum += __shfl_xor_sync(0xffffffffu, sum, o);
    float mu = sum * (1.0f / (float)DD);
    float vs = 0.f;
#pragma unroll
    for (int i = 0; i < 24; i++) {
        float d0 = y[i] - mu;
        y[i] = d0;
        vs += d0 * d0;
    }
#pragma unroll
    for (int o = 16; o > 0; o >>= 1) vs += __shfl_xor_sync(0xffffffffu, vs, o);
    float rstd = rsqrtf(vs * (1.0f / (float)DD) + 1e-5f);
#pragma unroll
    for (int i = 0; i < 24; i++) {
        int d = i * 32 + lane;
        orow[d] = y[i] * rstd * gamma[d] + beta[d];
    }
}

// ---------------- launch (spectral is launch #6 for ncu -s 5) ---------
extern "C" void kernel_launch(void* const* d_in, const int* in_sizes, int n_in,
                              void* d_out, int out_size) {
    const float* x = (const float*)d_in[0];
    const float* bf_g = (const float*)d_in[1];
    const float* bf_l = (const float*)d_in[2];
    const float* mb_g = (const float*)d_in[3];
    const float* mb_l = (const float*)d_in[4];
    const float* w1g = (const float*)d_in[5];
    const float* b1g = (const float*)d_in[6];
    const float* w2g = (const float*)d_in[7];
    const float* b2g = (const float*)d_in[8];
    const float* w1l = (const float*)d_in[9];
    const float* b1l = (const float*)d_in[10];
    const float* w2l = (const float*)d_in[11];
    const float* b2l = (const float*)d_in[12];
    const float* fw = (const float*)d_in[13];
    const float* gamma = (const float*)d_in[14];
    const float* beta = (const float*)d_in[15];
    float* out = (float*)d_out;

    tr_in_kernel<<<dim3(24, 64, 8), dim3(32, 8)>>>(x);                // 1
    mlp1_part_kernel<<<dim3(144, 8, 2), 128>>>(w1g, w1l);             // 2
    mlp2_part_kernel<<<dim3(98, 8), 128>>>(w2g, w2l, b1g, b1l);       // 3
    mlp2_fin_kernel<<<dim3(98, 8), 128>>>(b2g, b2l);                  // 4
    init_tw_kernel<<<5, 256>>>();                                     // 5
    spectral_kernel<<<BD * DD, 256>>>(bf_g, bf_l, mb_g, mb_l, fw);    // 6  <- profiled
    ln_fused_kernel<<<dim3(256, 8), 256>>>(x, gamma, beta, out);      // 7
}